// round 9
// baseline (speedup 1.0000x reference)
#include <cuda_runtime.h>

#define BATCH    8
#define NPTS     4096
#define THREADS  128
#define TI       16                      // thread-grid rows
#define TJ       8                       // thread-grid cols
#define RPT      8                       // rows per thread
#define RPAIRS   (RPT / 2)               // 4 packed row pairs
#define CPT      16                      // cols per thread
#define ROWTILE  128                     // rows per block (TI * RPT)
#define COLTILE  128                     // cols per iteration (TJ * CPT)
#define NROWT    (NPTS / ROWTILE)        // 32 row tiles
#define CHALF    2                       // col halves per row tile
#define ITERS    (NPTS / COLTILE / CHALF)// 16 col-tile iterations per block
#define NBLK     (BATCH * NROWT * CHALF) // 512 blocks = one full wave
#define NQ       (2 * BATCH * NPTS)      // 65536 result slots
#define RBLK     128                     // reduce blocks
#define CSTRIDE  (2 * CPT + 1)           // padded smem stride per tj (33)

__device__ unsigned g_max[NQ];   // reversed order keys; 0 == +inf identity
__device__ float    g_bsum[RBLK];
__device__ unsigned g_tick;      // zero-init; self-reset each replay

// ---- f32x2 helpers -------------------------------------------------------
__device__ __forceinline__ unsigned long long pk(float lo, float hi) {
    unsigned long long r;
    asm("mov.b64 %0, {%1, %2};" : "=l"(r)
        : "r"(__float_as_uint(lo)), "r"(__float_as_uint(hi)));
    return r;
}
__device__ __forceinline__ unsigned long long fma2(
    unsigned long long a, unsigned long long b, unsigned long long c) {
    unsigned long long d;
    asm("fma.rn.f32x2 %0, %1, %2, %3;" : "=l"(d) : "l"(a), "l"(b), "l"(c));
    return d;
}
__device__ __forceinline__ unsigned long long add2(
    unsigned long long a, unsigned long long b) {
    unsigned long long d;
    asm("add.rn.f32x2 %0, %1, %2;" : "=l"(d) : "l"(a), "l"(b));
    return d;
}
__device__ __forceinline__ void unpk(unsigned long long v, float& lo, float& hi) {
    unsigned a, b;
    asm("mov.b64 {%0, %1}, %2;" : "=r"(a), "=r"(b) : "l"(v));
    lo = __uint_as_float(a);
    hi = __uint_as_float(b);
}

// order-preserving float->uint key, REVERSED (smaller float -> larger key)
__device__ __forceinline__ unsigned rkey(float f) {
    unsigned u = __float_as_uint(f);
    unsigned k = (u >> 31) ? ~u : (u | 0x80000000u);
    return ~k;
}
__device__ __forceinline__ float rdecode(unsigned r) {
    unsigned k = ~r;
    unsigned u = (k >> 31) ? (k & 0x7FFFFFFFu) : ~k;
    return __uint_as_float(u);
}

// ---- kernel 1: fused tile kernel, 16 col-tiles per block -----------------
__global__ __launch_bounds__(THREADS, 5)
void chamfer_kernel(const float* __restrict__ pred,
                    const float* __restrict__ target)
{
    __shared__ ulonglong2 colbuf[TJ * CSTRIDE];     // ~4.2 KB candidate quads
    __shared__ float      colpart[4 * COLTILE];     // 2 KB per-warp col partials

    int bid = blockIdx.x;
    int h   = bid & (CHALF - 1);
    int rt  = (bid >> 1) & (NROWT - 1);
    int b   = bid >> 6;

    int tid = threadIdx.x;
    int tj  = tid & (TJ - 1);
    int ti  = tid >> 3;
    int wid = tid >> 5;

    // load this thread's 8 rows (pred points), packed two-rows-per-register
    int rbase = rt * ROWTILE + ti * RPT;
    const float* rb = pred + ((size_t)b * NPTS + rbase) * 3;
    unsigned long long pxp[RPAIRS], pyp[RPAIRS], pzp[RPAIRS], p2p[RPAIRS];
    #pragma unroll
    for (int rp = 0; rp < RPAIRS; rp++) {
        float x0 = rb[6 * rp + 0], y0 = rb[6 * rp + 1], z0 = rb[6 * rp + 2];
        float x1 = rb[6 * rp + 3], y1 = rb[6 * rp + 4], z1 = rb[6 * rp + 5];
        pxp[rp] = pk(x0, x1);
        pyp[rp] = pk(y0, y1);
        pzp[rp] = pk(z0, z1);
        p2p[rp] = pk(x0 * x0 + y0 * y0 + z0 * z0,
                     x1 * x1 + y1 * y1 + z1 * z1);
    }

    float rlo[RPAIRS], rhi[RPAIRS];
    #pragma unroll
    for (int rp = 0; rp < RPAIRS; rp++) { rlo[rp] = 3.0e38f; rhi[rp] = 3.0e38f; }

    int cb = tj * CSTRIDE;

    for (int it = 0; it < ITERS; it++) {
        int cs = h * ITERS + it;

        __syncthreads();   // prev colbuf consumed AND prev colpart combined
        {
            int c = tid;
            const float* p = target + ((size_t)b * NPTS + cs * COLTILE + c) * 3;
            float x = p[0], y = p[1], z = p[2];
            float t2 = x * x + y * y + z * z;
            int o = (c / CPT) * CSTRIDE + 2 * (c % CPT);
            colbuf[o + 0] = make_ulonglong2(pk(t2, t2), pk(-2.f * x, -2.f * x));
            colbuf[o + 1] = make_ulonglong2(pk(-2.f * y, -2.f * y), pk(-2.f * z, -2.f * z));
        }
        __syncthreads();

        float cmin[CPT];
        #pragma unroll
        for (int cc = 0; cc < CPT; cc++) cmin[cc] = 3.0e38f;

        #pragma unroll
        for (int cc = 0; cc < CPT; cc++) {
            ulonglong2 a  = colbuf[cb + 2 * cc + 0];   // (t2 dup, -2x dup)
            ulonglong2 bb = colbuf[cb + 2 * cc + 1];   // (-2y dup, -2z dup)
            #pragma unroll
            for (int rp = 0; rp < RPAIRS; rp++) {
                unsigned long long v =
                    fma2(bb.y, pzp[rp],
                    fma2(bb.x, pyp[rp],
                    fma2(a.y,  pxp[rp], add2(a.x, p2p[rp]))));
                float lo, hi;
                unpk(v, lo, hi);
                rlo[rp]  = fminf(rlo[rp], lo);
                rhi[rp]  = fminf(rhi[rp], hi);
                cmin[cc] = fminf(cmin[cc], fminf(lo, hi));
            }
        }

        // col mins: shuffle across in-warp ti (lane bits 3-4)
        #pragma unroll
        for (int cc = 0; cc < CPT; cc++) {
            float v = cmin[cc];
            v = fminf(v, __shfl_xor_sync(0xffffffffu, v, 8));
            v = fminf(v, __shfl_xor_sync(0xffffffffu, v, 16));
            cmin[cc] = v;
        }
        if ((tid & 24) == 0) {   // lanes 0..7 of each warp
            #pragma unroll
            for (int cc = 0; cc < CPT; cc++)
                colpart[wid * COLTILE + tj * CPT + cc] = cmin[cc];
        }
        __syncthreads();

        // combine 4 warp partials; 1 col per thread
        {
            int c = tid;
            float v = fminf(fminf(colpart[c],               colpart[COLTILE + c]),
                            fminf(colpart[2 * COLTILE + c], colpart[3 * COLTILE + c]));
            atomicMax(&g_max[(BATCH + b) * NPTS + cs * COLTILE + c], rkey(v));
        }
    }

    // ---- row epilogue ONCE per block: shuffle across tj (lane bits 0-2) --
    unsigned rowq = b * NPTS + rt * ROWTILE + ti * RPT;
    #pragma unroll
    for (int rp = 0; rp < RPAIRS; rp++) {
        float lo = rlo[rp], hi = rhi[rp];
        #pragma unroll
        for (int m = 1; m < 8; m <<= 1) {
            lo = fminf(lo, __shfl_xor_sync(0xffffffffu, lo, m));
            hi = fminf(hi, __shfl_xor_sync(0xffffffffu, hi, m));
        }
        if (tj == 0) {
            atomicMax(&g_max[rowq + 2 * rp + 0], rkey(lo));
            atomicMax(&g_max[rowq + 2 * rp + 1], rkey(hi));
        }
    }
}

// ---- kernel 2: decode + sum + self-reset + ticket finish -----------------
__global__ __launch_bounds__(256)
void reduce_kernel(float* __restrict__ out)
{
    __shared__ float wsum[8];
    __shared__ int   is_last;
    int tid = threadIdx.x;
    int i2  = (blockIdx.x * 256 + tid) * 2;

    uint2 k = *(const uint2*)&g_max[i2];
    *(uint2*)&g_max[i2] = make_uint2(0u, 0u);   // reset for replay

    float sum = rdecode(k.x) + rdecode(k.y);

    #pragma unroll
    for (int off = 16; off > 0; off >>= 1)
        sum += __shfl_down_sync(0xffffffffu, sum, off);
    if ((tid & 31) == 0) wsum[tid >> 5] = sum;
    __syncthreads();

    if (tid == 0) {
        float s = 0.0f;
        #pragma unroll
        for (int w = 0; w < 8; w++) s += wsum[w];
        g_bsum[blockIdx.x] = s;
        __threadfence();
        unsigned t = atomicAdd(&g_tick, 1u);
        is_last = (t == RBLK - 1);
    }
    __syncthreads();

    if (is_last && tid < 32) {
        __threadfence();
        float s = 0.0f;
        #pragma unroll
        for (int r = 0; r < RBLK / 32; r++)
            s += *((volatile float*)&g_bsum[r * 32 + tid]);
        #pragma unroll
        for (int off = 16; off > 0; off >>= 1)
            s += __shfl_down_sync(0xffffffffu, s, off);
        if (tid == 0) {
            out[0] = s * (1.0f / (float)(BATCH * NPTS));
            g_tick = 0;   // self-reset for next graph replay
        }
    }
}

extern "C" void kernel_launch(void* const* d_in, const int* in_sizes, int n_in,
                              void* d_out, int out_size)
{
    const float* pred   = (const float*)d_in[0];
    const float* target = (const float*)d_in[1];
    float* out = (float*)d_out;

    chamfer_kernel<<<NBLK, THREADS>>>(pred, target);
    reduce_kernel<<<RBLK, 256>>>(out);
}